// round 8
// baseline (speedup 1.0000x reference)
#include <cuda_runtime.h>
#include <cuda_fp16.h>
#include <math.h>

// Problem constants
#define B 8
#define CIN 128
#define D2 256
#define HH 128
#define WW 128
#define NPIX (HH*WW)          // 16384
#define HEADS 8
#define CH 32                  // D2/HEADS
#define GCH 8                  // gram chunks
#define GCHLEN (NPIX/GCH)      // 2048

// ---------------- scratch (device globals; no allocation) ----------------
__device__ __half g_t[3ull*B*D2*NPIX];    // conv1x1 outputs, fp16
__device__ float  g_qkv[3ull*B*D2*NPIX];  // post-depthwise q,k,v (fp32)
__device__ float  g_Sp[64*GCH*1024];      // gram partials [bh][chunk][32*32]
__device__ float  g_np2[2*2048*4];        // sq-sum partials [stream*2048+plane][4]
__device__ float  g_M[B*128*D2];          // folded projection weights [b][128][256]

// ---------------- cp.async helpers ----------------
__device__ __forceinline__ unsigned smem_u32(const void* p) {
    unsigned a;
    asm("{ .reg .u64 t; cvta.to.shared.u64 t, %1; cvt.u32.u64 %0, t; }" : "=r"(a) : "l"(p));
    return a;
}
#define CP_ASYNC8(dst, src)  asm volatile("cp.async.ca.shared.global [%0], [%1], 8;\n"  :: "r"(dst), "l"(src))
#define CP_ASYNC16(dst, src) asm volatile("cp.async.cg.shared.global [%0], [%1], 16;\n" :: "r"(dst), "l"(src))
#define CP_COMMIT()          asm volatile("cp.async.commit_group;\n")
#define CP_WAIT1()           asm volatile("cp.async.wait_group 1;\n")
#define CP_WAIT0()           asm volatile("cp.async.wait_group 0;\n")

#define MMA_TF32(d0,d1,d2,d3,a0,a1,a2,a3,b0,b1) \
    asm volatile("mma.sync.aligned.m16n8k8.row.col.f32.tf32.tf32.f32 " \
        "{%0,%1,%2,%3}, {%4,%5,%6,%7}, {%8,%9}, {%0,%1,%2,%3};\n" \
        : "+f"(d0), "+f"(d1), "+f"(d2), "+f"(d3) \
        : "r"(a0), "r"(a1), "r"(a2), "r"(a3), "r"(b0), "r"(b1))

// =====================================================================
// tf32 GEMM + bias, cp.async double-buffered, dynamic smem, templated
// output type. z = s*8 + b : A = A{s} + b*sA, B = B{s} + b*sB,
// bias = bias{s}, C = Cbase + z*sC. Block tile 128x128, K-tile 32.
// =====================================================================
#define GK 32
#define AS_STRIDE 36
#define BS_STRIDE 136
#define AS_STAGE (128 * AS_STRIDE)
#define BS_STAGE (GK * BS_STRIDE)
#define SMEM_GEMM ((2 * AS_STAGE + 2 * BS_STAGE) * 4)  // 71680 bytes

template<typename OutT>
__global__ __launch_bounds__(256)
void gemm_tf32_bias(const float* __restrict__ A0, const float* __restrict__ A1,
                    const float* __restrict__ A2, long sA,
                    const float* __restrict__ B0, const float* __restrict__ B1,
                    const float* __restrict__ B2, long sB,
                    OutT* __restrict__ C, long sC,
                    const float* __restrict__ bias0, const float* __restrict__ bias1,
                    const float* __restrict__ bias2,
                    int M, int K, int N)
{
    extern __shared__ float dynsm[];
    float* AsBase = dynsm;
    float* BsBase = dynsm + 2 * AS_STAGE;

    const int z = blockIdx.z;
    const int s = z >> 3;
    const int bloc = z & 7;
    const float* A    = ((s == 0) ? A0 : (s == 1) ? A1 : A2) + bloc * sA;
    const float* Bm   = ((s == 0) ? B0 : (s == 1) ? B1 : B2) + bloc * sB;
    const float* bias = (s == 0) ? bias0 : (s == 1) ? bias1 : bias2;
    C += (long)z * sC;

    const int m0 = blockIdx.y * 128;
    const int n0 = blockIdx.x * 128;

    const int tid  = threadIdx.x;
    const int wid  = tid >> 5;
    const int lane = tid & 31;
    const int wm0 = (wid >> 2) * 64;
    const int wn0 = (wid & 3) * 32;
    const int r = lane >> 2;
    const int c = lane & 3;

    float acc[4][4][4];
#pragma unroll
    for (int mt = 0; mt < 4; mt++)
#pragma unroll
        for (int nt = 0; nt < 4; nt++)
#pragma unroll
            for (int i = 0; i < 4; i++) acc[mt][nt][i] = 0.f;

    const int nIter = K / GK;

    auto issue = [&](int t) {
        const int st = t & 1;
        const int k0 = t * GK;
        float* As = AsBase + st * AS_STAGE;
        float* Bs = BsBase + st * BS_STAGE;
#pragma unroll
        for (int it = 0; it < 8; it++) {
            int lin = it * 256 + tid;
            int row = lin >> 4;
            int c2  = (lin & 15) * 2;
            CP_ASYNC8(smem_u32(As + row * AS_STRIDE + c2),
                      A + (long)(m0 + row) * K + k0 + c2);
        }
#pragma unroll
        for (int it = 0; it < 4; it++) {
            int lin = it * 256 + tid;
            int row = lin >> 5;
            int c4  = (lin & 31) * 4;
            CP_ASYNC16(smem_u32(Bs + row * BS_STRIDE + c4),
                       Bm + (long)(k0 + row) * N + n0 + c4);
        }
    };

    issue(0);
    CP_COMMIT();

    for (int t = 0; t < nIter; t++) {
        if (t + 1 < nIter) { issue(t + 1); CP_COMMIT(); CP_WAIT1(); }
        else               { CP_WAIT0(); }
        __syncthreads();

        const int st = t & 1;
        const float* As = AsBase + st * AS_STAGE;
        const float* Bs = BsBase + st * BS_STAGE;
#pragma unroll
        for (int ks = 0; ks < GK; ks += 8) {
            unsigned af[4][4], bf[4][2];
#pragma unroll
            for (int mt = 0; mt < 4; mt++) {
                int mr = wm0 + mt * 16 + r;
                af[mt][0] = __float_as_uint(As[(mr    ) * AS_STRIDE + ks + c    ]);
                af[mt][1] = __float_as_uint(As[(mr + 8) * AS_STRIDE + ks + c    ]);
                af[mt][2] = __float_as_uint(As[(mr    ) * AS_STRIDE + ks + c + 4]);
                af[mt][3] = __float_as_uint(As[(mr + 8) * AS_STRIDE + ks + c + 4]);
            }
#pragma unroll
            for (int nt = 0; nt < 4; nt++) {
                int nc = wn0 + nt * 8 + r;
                bf[nt][0] = __float_as_uint(Bs[(ks + c    ) * BS_STRIDE + nc]);
                bf[nt][1] = __float_as_uint(Bs[(ks + c + 4) * BS_STRIDE + nc]);
            }
#pragma unroll
            for (int mt = 0; mt < 4; mt++)
#pragma unroll
                for (int nt = 0; nt < 4; nt++)
                    MMA_TF32(acc[mt][nt][0], acc[mt][nt][1], acc[mt][nt][2], acc[mt][nt][3],
                             af[mt][0], af[mt][1], af[mt][2], af[mt][3],
                             bf[nt][0], bf[nt][1]);
        }
        __syncthreads();
    }

#pragma unroll
    for (int mt = 0; mt < 4; mt++) {
        int row0 = m0 + wm0 + mt * 16 + r;
        float bv0 = bias[row0];
        float bv8 = bias[row0 + 8];
#pragma unroll
        for (int nt = 0; nt < 4; nt++) {
            int col = n0 + wn0 + nt * 8 + 2 * c;
            if constexpr (sizeof(OutT) == 2) {
                __half2 h0 = __floats2half2_rn(acc[mt][nt][0] + bv0, acc[mt][nt][1] + bv0);
                __half2 h8 = __floats2half2_rn(acc[mt][nt][2] + bv8, acc[mt][nt][3] + bv8);
                *reinterpret_cast<__half2*>((__half*)C + (long)row0 * N + col)       = h0;
                *reinterpret_cast<__half2*>((__half*)C + (long)(row0 + 8) * N + col) = h8;
            } else {
                float2 v0 = { acc[mt][nt][0] + bv0, acc[mt][nt][1] + bv0 };
                float2 v8 = { acc[mt][nt][2] + bv8, acc[mt][nt][3] + bv8 };
                *reinterpret_cast<float2*>((float*)C + (long)row0 * N + col)       = v0;
                *reinterpret_cast<float2*>((float*)C + (long)(row0 + 8) * N + col) = v8;
            }
        }
    }
}

// =====================================================================
// depthwise 3x3 SAME — register/shuffle version, no smem for data.
// fp16 input, fp32 output. Warp = 4 rows of one plane; lane L = cols 4L..4L+3.
// Also accumulates per-(plane, rowgroup) sum of squares for q/k norms.
// grid: (4, 3*B*D2), block 256 (8 warps x 4 rows = 32 rows)
// =====================================================================
__global__ __launch_bounds__(256)
void dwconv3x3_v4(const __half* __restrict__ in,
                  float* __restrict__ out,
                  const float* __restrict__ w0, const float* __restrict__ b0,
                  const float* __restrict__ w1, const float* __restrict__ b1,
                  const float* __restrict__ w2, const float* __restrict__ b2,
                  float* __restrict__ np2)
{
    const int z = blockIdx.y;                 // s*2048 + b*256 + oc
    const int s = z >> 11;
    const int oc = z & (D2 - 1);
    const float* wsel = (s == 0) ? w0 : (s == 1) ? w1 : w2;
    const float* bsel = (s == 0) ? b0 : (s == 1) ? b1 : b2;

    float w9[9];
#pragma unroll
    for (int t = 0; t < 9; t++) w9[t] = wsel[oc * 9 + t];
    const float bv = bsel[oc];

    const __half* ip = in + (long)z * NPIX;
    float* op = out + (long)z * NPIX;

    const int tid  = threadIdx.x;
    const int warp = tid >> 5;
    const int lane = tid & 31;
    const int row0 = blockIdx.x * 32 + warp * 4;

    auto loadwin = [&](int gr, float* w6) {
        if (gr < 0 || gr >= HH) {             // uniform across warp
#pragma unroll
            for (int j = 0; j < 6; j++) w6[j] = 0.f;
            return;
        }
        uint2 u = *reinterpret_cast<const uint2*>(ip + gr * WW + lane * 4);
        float2 f0 = __half22float2(*reinterpret_cast<__half2*>(&u.x));
        float2 f1 = __half22float2(*reinterpret_cast<__half2*>(&u.y));
        float left  = __shfl_up_sync(0xffffffffu, f1.y, 1);
        float right = __shfl_down_sync(0xffffffffu, f0.x, 1);
        if (lane == 0)  left  = 0.f;
        if (lane == 31) right = 0.f;
        w6[0] = left; w6[1] = f0.x; w6[2] = f0.y; w6[3] = f1.x; w6[4] = f1.y; w6[5] = right;
    };

    float wa[6], wb[6], wc[6];
    loadwin(row0 - 1, wa);
    loadwin(row0,     wb);

    float sq = 0.f;
#pragma unroll
    for (int i = 0; i < 4; i++) {
        loadwin(row0 + 1 + i, wc);
        float4 o;
        float* po = &o.x;
#pragma unroll
        for (int j = 0; j < 4; j++) {
            float a = bv;
#pragma unroll
            for (int dx = 0; dx < 3; dx++) {
                a = fmaf(wa[j + dx], w9[dx],     a);
                a = fmaf(wb[j + dx], w9[3 + dx], a);
                a = fmaf(wc[j + dx], w9[6 + dx], a);
            }
            po[j] = a;
            sq = fmaf(a, a, sq);
        }
        *reinterpret_cast<float4*>(op + (row0 + i) * WW + lane * 4) = o;
#pragma unroll
        for (int j = 0; j < 6; j++) { wa[j] = wb[j]; wb[j] = wc[j]; }
    }

    // block-reduce sum of squares (for q/k norm; streams 0,1 only)
#pragma unroll
    for (int off = 16; off > 0; off >>= 1)
        sq += __shfl_xor_sync(0xffffffffu, sq, off);
    __shared__ float wsum[8];
    if (lane == 0) wsum[warp] = sq;
    __syncthreads();
    if (tid == 0 && z < 2 * B * D2) {
        float t = 0.f;
#pragma unroll
        for (int w = 0; w < 8; w++) t += wsum[w];
        np2[z * 4 + blockIdx.x] = t;
    }
}

// =====================================================================
// Gram via tf32 mma: S[c][d] += q[c][px] * k[d][px] over a 2048-px chunk.
// grid (GCH, 64), block 256 (8 warps). Tile 32x64 px in smem; warp j takes
// px-slice 8j..8j+8. Cross-warp reduction through smem at the end.
// =====================================================================
__global__ __launch_bounds__(256)
void gram_mma(const float* __restrict__ qg,
              const float* __restrict__ kg,
              float* __restrict__ Sp)
{
    const int bh = blockIdx.y;
    const int chunk = blockIdx.x;
    const float* qb = qg + (long)bh * CH * NPIX + chunk * GCHLEN;
    const float* kb = kg + (long)bh * CH * NPIX + chunk * GCHLEN;

    __shared__ __align__(16) char gsm[8 * 1024 * 4];   // 32KB: tiles (17KB) then partials
    float* qs = reinterpret_cast<float*>(gsm);          // [32][68]
    float* ks = qs + 32 * 68;                           // [32][68]

    const int tid  = threadIdx.x;
    const int wid  = tid >> 5;
    const int lane = tid & 31;
    const int r = lane >> 2;
    const int c = lane & 3;
    const int px = wid * 8;      // this warp's k-slice within the 64-px tile

    float acc[2][4][4];
#pragma unroll
    for (int mt = 0; mt < 2; mt++)
#pragma unroll
        for (int nt = 0; nt < 4; nt++)
#pragma unroll
            for (int i = 0; i < 4; i++) acc[mt][nt][i] = 0.f;

    for (int t0 = 0; t0 < GCHLEN; t0 += 64) {
#pragma unroll
        for (int it = 0; it < 2; it++) {
            int lin = it * 256 + tid;
            int row = lin >> 4;
            int c4  = (lin & 15) * 4;
            CP_ASYNC16(smem_u32(qs + row * 68 + c4), qb + (long)row * NPIX + t0 + c4);
            CP_ASYNC16(smem_u32(ks + row * 68 + c4), kb + (long)row * NPIX + t0 + c4);
        }
        CP_COMMIT();
        CP_WAIT0();
        __syncthreads();

        unsigned af[2][4], bf[4][2];
#pragma unroll
        for (int mt = 0; mt < 2; mt++) {
            int mr = mt * 16 + r;
            af[mt][0] = __float_as_uint(qs[(mr    ) * 68 + px + c    ]);
            af[mt][1] = __float_as_uint(qs[(mr + 8) * 68 + px + c    ]);
            af[mt][2] = __float_as_uint(qs[(mr    ) * 68 + px + c + 4]);
            af[mt][3] = __float_as_uint(qs[(mr + 8) * 68 + px + c + 4]);
        }
#pragma unroll
        for (int nt = 0; nt < 4; nt++) {
            int nc = nt * 8 + r;
            bf[nt][0] = __float_as_uint(ks[nc * 68 + px + c    ]);
            bf[nt][1] = __float_as_uint(ks[nc * 68 + px + c + 4]);
        }
#pragma unroll
        for (int mt = 0; mt < 2; mt++)
#pragma unroll
            for (int nt = 0; nt < 4; nt++)
                MMA_TF32(acc[mt][nt][0], acc[mt][nt][1], acc[mt][nt][2], acc[mt][nt][3],
                         af[mt][0], af[mt][1], af[mt][2], af[mt][3],
                         bf[nt][0], bf[nt][1]);
        __syncthreads();
    }

    // cross-warp reduce: write each warp's 32x32 partial to smem, sum 8-way
    float* part = reinterpret_cast<float*>(gsm);        // [8][1024]
#pragma unroll
    for (int mt = 0; mt < 2; mt++) {
        int m = mt * 16 + r;
#pragma unroll
        for (int nt = 0; nt < 4; nt++) {
            int n = nt * 8 + 2 * c;
            part[wid * 1024 + m * 32 + n]           = acc[mt][nt][0];
            part[wid * 1024 + m * 32 + n + 1]       = acc[mt][nt][1];
            part[wid * 1024 + (m + 8) * 32 + n]     = acc[mt][nt][2];
            part[wid * 1024 + (m + 8) * 32 + n + 1] = acc[mt][nt][3];
        }
    }
    __syncthreads();

    const int e = tid * 4;
    float4 ssum = *reinterpret_cast<float4*>(&part[e]);
#pragma unroll
    for (int w = 1; w < 8; w++) {
        float4 v = *reinterpret_cast<float4*>(&part[w * 1024 + e]);
        ssum.x += v.x; ssum.y += v.y; ssum.z += v.z; ssum.w += v.w;
    }
    *reinterpret_cast<float4*>(&Sp[((long)bh * GCH + chunk) * 1024 + e]) = ssum;
}

// ---------------- reduce + softmax + fold attention into projection ----
__global__ void softmax_fold(const float* __restrict__ Sp,
                             const float* __restrict__ np2,
                             const float* __restrict__ P,
                             float* __restrict__ Mout)
{
    const int bh = blockIdx.x;
    const int b  = bh >> 3;
    const int hh = bh & 7;
    const int tid = threadIdx.x;

    __shared__ float sS[1024];
    __shared__ float qn[32], kn[32];

    for (int e = tid; e < 1024; e += 128) {
        float s = 0.f;
        for (int j = 0; j < GCH; j++) s += Sp[((long)bh * GCH + j) * 1024 + e];
        sS[e] = s;
    }
    if (tid < 64) {
        int ch = tid & 31;
        int zz = ((tid < 32) ? 0 : 2048) + b * 256 + hh * 32 + ch;
        float s = 0.f;
#pragma unroll
        for (int j = 0; j < 4; j++) s += np2[zz * 4 + j];
        float nv = fmaxf(sqrtf(s), 1e-12f);
        if (tid < 32) qn[ch] = nv; else kn[ch] = nv;
    }
    __syncthreads();

    const float scale = 0.25f;   // 1/sqrt(128/8)
    if (tid < 32) {
        const int c = tid;
        float inv_q = 1.f / qn[c];
        float vals[32];
        float mx = -1e30f;
#pragma unroll
        for (int d = 0; d < 32; d++) {
            float v = sS[c * 32 + d] * scale * inv_q / kn[d];
            vals[d] = v;
            mx = fmaxf(mx, v);
        }
        float sum = 0.f;
#pragma unroll
        for (int d = 0; d < 32; d++) { vals[d] = expf(vals[d] - mx); sum += vals[d]; }
        float inv = 1.f / sum;
#pragma unroll
        for (int d = 0; d < 32; d++) sS[c * 32 + d] = vals[d] * inv;
    }
    __syncthreads();

    float prow[32];
#pragma unroll
    for (int c = 0; c < 32; c++) prow[c] = P[tid * D2 + hh * 32 + c];
#pragma unroll 4
    for (int d = 0; d < 32; d++) {
        float a = 0.f;
#pragma unroll
        for (int c = 0; c < 32; c++) a = fmaf(prow[c], sS[c * 32 + d], a);
        Mout[((long)b * 128 + tid) * D2 + hh * 32 + d] = a;
    }
}

// ---------------- launch ----------------
extern "C" void kernel_launch(void* const* d_in, const int* in_sizes, int n_in,
                              void* d_out, int out_size)
{
    const float* x[3]  = { (const float*)d_in[0], (const float*)d_in[1], (const float*)d_in[2] };
    const float* w1[3] = { (const float*)d_in[3], (const float*)d_in[5], (const float*)d_in[7] };
    const float* b1[3] = { (const float*)d_in[4], (const float*)d_in[6], (const float*)d_in[8] };
    const float* wd[3] = { (const float*)d_in[9], (const float*)d_in[11], (const float*)d_in[13] };
    const float* bd[3] = { (const float*)d_in[10], (const float*)d_in[12], (const float*)d_in[14] };
    const float* pw = (const float*)d_in[15];
    const float* pb = (const float*)d_in[16];
    float* out = (float*)d_out;

    __half *t_ptr;
    float *qkv_ptr, *Sp_ptr, *np2_ptr, *M_ptr;
    cudaGetSymbolAddress((void**)&t_ptr,   g_t);
    cudaGetSymbolAddress((void**)&qkv_ptr, g_qkv);
    cudaGetSymbolAddress((void**)&Sp_ptr,  g_Sp);
    cudaGetSymbolAddress((void**)&np2_ptr, g_np2);
    cudaGetSymbolAddress((void**)&M_ptr,   g_M);

    cudaFuncSetAttribute(gemm_tf32_bias<__half>,
                         cudaFuncAttributeMaxDynamicSharedMemorySize, SMEM_GEMM);
    cudaFuncSetAttribute(gemm_tf32_bias<float>,
                         cudaFuncAttributeMaxDynamicSharedMemorySize, SMEM_GEMM);

    const long planeStride = (long)D2 * NPIX;
    const long streamStride = (long)B * planeStride;

    // 1) three pointwise convs merged: z = s*8 + b, fp16 output
    {
        dim3 grid(NPIX / 128, D2 / 128, 24);
        gemm_tf32_bias<__half><<<grid, 256, SMEM_GEMM>>>(
            w1[0], w1[1], w1[2], 0,
            x[0], x[1], x[2], (long)CIN * NPIX,
            t_ptr, planeStride,
            b1[0], b1[1], b1[2],
            D2, CIN, NPIX);
    }
    // 2) depthwise 3x3 (fp16 in, fp32 out) + norm partials
    {
        dim3 grid(4, 3 * B * D2);
        dwconv3x3_v4<<<grid, 256>>>(t_ptr, qkv_ptr,
                                    wd[0], bd[0], wd[1], bd[1], wd[2], bd[2],
                                    np2_ptr);
    }
    // 3) gram via tensor cores
    {
        dim3 grid(GCH, 64);
        gram_mma<<<grid, 256>>>(qkv_ptr + 0 * streamStride,
                                qkv_ptr + 1 * streamStride,
                                Sp_ptr);
    }
    // 4) softmax + fold attention into projection weights
    softmax_fold<<<64, 128>>>(Sp_ptr, np2_ptr, pw, M_ptr);

    // 5) final: out[b] = M[b](128x256) @ v[b](256x16384) + pb
    {
        dim3 grid(NPIX / 128, 1, 8);
        gemm_tf32_bias<float><<<grid, 256, SMEM_GEMM>>>(
            M_ptr, M_ptr, M_ptr, (long)128 * D2,
            qkv_ptr + 2 * streamStride, qkv_ptr + 2 * streamStride,
            qkv_ptr + 2 * streamStride, planeStride,
            out, (long)CIN * NPIX,
            pb, pb, pb,
            128, D2, NPIX);
    }
}